// round 10
// baseline (speedup 1.0000x reference)
#include <cuda_runtime.h>
#include <math.h>
#include <stdint.h>

// SlotAttention GB300 — Round 9: smem-staged attention pass. Each block stages
// a 64x256 x̂ tile into padded smem ONCE and feeds both logits/softmax (phase 1)
// and update-accumulation (phase 2) from it. q kept in two bank-offset smem
// copies for conflict-free LDS.128 across slot-groups. All fp32.

#define Bb 64
#define Nn 4096
#define Dd 256
#define Kk 15
#define Hh 512
#define BN_TOT (Bb * Nn)   // 262144
#define BK_TOT (Bb * Kk)   // 960
#define NCH 4              // n-chunks per batch (1024 n each)
#define NSUB 16            // sub-chunks of 64 n per chunk

#define XS_PAD 260         // x̂ row stride (floats): float4-aligned, bank-spread
#define QS_PAD 260
#define Q_COPY2 4164       // float offset of 2nd q copy (bank shift 4)
#define AS_PAD 68

// smem layout (floats): xs[64*260] | qs[2 copies] | as[16*68]
#define SM_XS 0
#define SM_QS (64 * XS_PAD)                     // 16640
#define SM_AS (SM_QS + Q_COPY2 + 16 * QS_PAD)   // 16640+4164+4160 = 24964
#define SM_TOTAL (SM_AS + 16 * AS_PAD)          // 26052 floats = 104208 B

// ---------------- scratch ----------------
__device__ float g_xln[(size_t)BN_TOT * Dd];      // 256 MiB
__device__ float g_wqk[Dd * Dd];                  // [e][d] = Σ_j Wk[j,e]·Wq[j,d]
__device__ float g_wiv[3 * Dd * Dd];              // [g][e] = Σ_d w_ih[g,d]·Wv[d,e]
__device__ float g_slots[BK_TOT * Dd];
__device__ float g_q[BK_TOT * Dd];
__device__ float g_part[BK_TOT * NCH];
__device__ float g_updpart[(size_t)NCH * BK_TOT * Dd];  // 3.9 MB

// ---------------- helpers ----------------
__device__ __forceinline__ float warp_sum(float v) {
#pragma unroll
    for (int o = 16; o > 0; o >>= 1) v += __shfl_xor_sync(0xffffffffu, v, o);
    return v;
}
__device__ __forceinline__ float sigmoidf_(float x) { return 1.0f / (1.0f + __expf(-x)); }

template <int K4>
__device__ __forceinline__ void dot4(float acc[8], const float* S, int srow,
                                     const float* __restrict__ Wrow) {
    const float4* w4 = (const float4*)Wrow;
#pragma unroll 4
    for (int d4 = 0; d4 < K4; d4++) {
        float4 w = w4[d4];
#pragma unroll
        for (int r = 0; r < 8; r++) {
            const float4 sv = *(const float4*)(S + r * srow + d4 * 4);
            acc[r] += sv.x * w.x + sv.y * w.y + sv.z * w.z + sv.w * w.w;
        }
    }
}

__device__ __forceinline__ void warp_ln_row(const float* src, float* dst,
                                            const float* __restrict__ w,
                                            const float* __restrict__ b, int lane) {
    float vals[8];
    float s = 0.f, s2 = 0.f;
#pragma unroll
    for (int k = 0; k < 8; k++) {
        float v = src[lane + 32 * k];
        vals[k] = v; s += v; s2 += v * v;
    }
    s = warp_sum(s); s2 = warp_sum(s2);
    float m = s * (1.0f / 256.0f);
    float rs = rsqrtf(s2 * (1.0f / 256.0f) - m * m + 1e-5f);
#pragma unroll
    for (int k = 0; k < 8; k++) {
        int d = lane + 32 * k;
        dst[d] = (vals[k] - m) * rs * w[d] + b[d];
    }
}

// ---------------- big LN over inputs ----------------
__global__ void ln_apply_kernel(const float* __restrict__ x, float* __restrict__ y,
                                const float* __restrict__ w, const float* __restrict__ bb) {
    int row = blockIdx.x * 8 + threadIdx.y;
    int lane = threadIdx.x;
    warp_ln_row(x + (size_t)row * Dd, y + (size_t)row * Dd, w, bb, lane);
}

// ---------------- precompute: C[e][d] = Σ_j X[j][e]·Y[j][d]  (XᵀY) ----------------
__global__ __launch_bounds__(256) void atb_kernel(const float* __restrict__ X,
                                                  const float* __restrict__ Y,
                                                  float* __restrict__ C) {
    __shared__ float Xs[16][68];
    __shared__ float Ys[16][68];
    int e0 = blockIdx.x * 64, d0 = blockIdx.y * 64;
    int tid = threadIdx.x;
    int row_t = tid >> 4, col_t = tid & 15;
    int jr = tid >> 4, c4 = (tid & 15) << 2;
    float acc[4][4];
#pragma unroll
    for (int i = 0; i < 4; i++)
#pragma unroll
        for (int j = 0; j < 4; j++) acc[i][j] = 0.f;
    for (int jb = 0; jb < 256; jb += 16) {
        float4 xv = *(const float4*)(X + (size_t)(jb + jr) * Dd + e0 + c4);
        Xs[jr][c4 + 0] = xv.x; Xs[jr][c4 + 1] = xv.y;
        Xs[jr][c4 + 2] = xv.z; Xs[jr][c4 + 3] = xv.w;
        float4 yv = *(const float4*)(Y + (size_t)(jb + jr) * Dd + d0 + c4);
        Ys[jr][c4 + 0] = yv.x; Ys[jr][c4 + 1] = yv.y;
        Ys[jr][c4 + 2] = yv.z; Ys[jr][c4 + 3] = yv.w;
        __syncthreads();
#pragma unroll
        for (int k = 0; k < 16; k++)
#pragma unroll
            for (int i = 0; i < 4; i++)
#pragma unroll
                for (int j = 0; j < 4; j++)
                    acc[i][j] += Xs[k][row_t * 4 + i] * Ys[k][col_t * 4 + j];
        __syncthreads();
    }
#pragma unroll
    for (int i = 0; i < 4; i++)
#pragma unroll
        for (int j = 0; j < 4; j++)
            C[(size_t)(e0 + row_t * 4 + i) * Dd + d0 + col_t * 4 + j] = acc[i][j];
}

// ---------------- precompute: C[g][e] = Σ_d A[g][d]·B[d][e]  (A·B) ----------------
__global__ __launch_bounds__(256) void ab_kernel(const float* __restrict__ A,
                                                 const float* __restrict__ B,
                                                 float* __restrict__ C) {
    __shared__ float As[16][68];
    __shared__ float Bs[16][68];
    int g0 = blockIdx.x * 64, e0 = blockIdx.y * 64;
    int tid = threadIdx.x;
    int row_t = tid >> 4, col_t = tid & 15;
    int r = tid >> 2, k4 = (tid & 3) << 2;
    int jr = tid >> 4, c4 = (tid & 15) << 2;
    float acc[4][4];
#pragma unroll
    for (int i = 0; i < 4; i++)
#pragma unroll
        for (int j = 0; j < 4; j++) acc[i][j] = 0.f;
    for (int db = 0; db < 256; db += 16) {
        float4 av = *(const float4*)(A + (size_t)(g0 + r) * Dd + db + k4);
        As[k4 + 0][r] = av.x; As[k4 + 1][r] = av.y;
        As[k4 + 2][r] = av.z; As[k4 + 3][r] = av.w;
        float4 bv = *(const float4*)(B + (size_t)(db + jr) * Dd + e0 + c4);
        Bs[jr][c4 + 0] = bv.x; Bs[jr][c4 + 1] = bv.y;
        Bs[jr][c4 + 2] = bv.z; Bs[jr][c4 + 3] = bv.w;
        __syncthreads();
#pragma unroll
        for (int k = 0; k < 16; k++)
#pragma unroll
            for (int i = 0; i < 4; i++)
#pragma unroll
                for (int j = 0; j < 4; j++)
                    acc[i][j] += As[k][row_t * 4 + i] * Bs[k][col_t * 4 + j];
        __syncthreads();
    }
#pragma unroll
    for (int i = 0; i < 4; i++)
#pragma unroll
        for (int j = 0; j < 4; j++)
            C[(size_t)(g0 + row_t * 4 + i) * Dd + e0 + col_t * 4 + j] = acc[i][j];
}

// ---------------- slots init ----------------
__global__ void slots_init_kernel(const float* __restrict__ mu,
                                  const float* __restrict__ ls,
                                  const float* __restrict__ noise) {
    int i = blockIdx.x * 256 + threadIdx.x;
    int kd = i % (Kk * Dd);
    g_slots[i] = mu[kd] + __expf(ls[kd]) * noise[i];
}

// ---------------- ln_slots + q (before first iteration) ----------------
__global__ __launch_bounds__(256) void slot_lnq_kernel(const float* __restrict__ lns_w,
                                                       const float* __restrict__ lns_b) {
    __shared__ float a_s[8][256];
    int t = threadIdx.x, lane = t & 31, wid = t >> 5;
    int row0 = blockIdx.x * 8;
    warp_ln_row(g_slots + (size_t)(row0 + wid) * Dd, &a_s[wid][0], lns_w, lns_b, lane);
    __syncthreads();
    float qa[8] = {0, 0, 0, 0, 0, 0, 0, 0};
    dot4<64>(qa, &a_s[0][0], 256, g_wqk + (size_t)t * Dd);
#pragma unroll
    for (int r = 0; r < 8; r++) g_q[(size_t)(row0 + r) * Dd + t] = qa[r];
}

// ---------------- smem-staged fused attention pass ----------------
// grid (NCH, Bb), block 256, dyn smem SM_TOTAL floats.
__global__ __launch_bounds__(256) void attn_pass_kernel(const float* __restrict__ q,
                                                        const float* __restrict__ xln,
                                                        float* __restrict__ attn_out,
                                                        int final_pass) {
    extern __shared__ float sm[];
    float* xs = sm + SM_XS;
    float* qs = sm + SM_QS;
    float* as_ = sm + SM_AS;
    int b = blockIdx.y, chunk = blockIdx.x, t = threadIdx.x;
    int n_loc = t >> 2, g = t & 3;     // phase-1 mapping: 64 n x 4 slot-quads
    int s0 = g * 4;
    const float* qsg = qs + ((g >= 2) ? Q_COPY2 : 0);

    // stage q (16 rows incl. zero pad row s=15) into both copies
    {
        const float4* qb4 = (const float4*)(q + (size_t)b * Kk * Dd);
        float4 z = make_float4(0.f, 0.f, 0.f, 0.f);
        for (int i = t; i < 16 * 64; i += 256) {
            int s = i >> 6, d4 = i & 63;
            float4 v = (s < Kk) ? qb4[s * 64 + d4] : z;
            *(float4*)(qs + s * QS_PAD + 4 * d4) = v;
            *(float4*)(qs + Q_COPY2 + s * QS_PAD + 4 * d4) = v;
        }
    }

    float acc[Kk];
#pragma unroll
    for (int s = 0; s < Kk; s++) acc[s] = 0.f;
    float psum = 0.f;

    for (int sub = 0; sub < NSUB; sub++) {
        __syncthreads();   // guards xs/as reuse vs prev sub-chunk phase 2
        // stage x̂ tile: 64 rows x 256 d
        const float4* xg = (const float4*)(xln +
            ((size_t)b * Nn + chunk * (NSUB * 64) + sub * 64) * Dd);
#pragma unroll
        for (int i = t; i < 64 * 64; i += 256) {
            int r = i >> 6, d4 = i & 63;
            *(float4*)(xs + r * XS_PAD + 4 * d4) = xg[(size_t)r * 64 + d4];
        }
        __syncthreads();

        // phase 1: logits for (n_loc, slots s0..s0+3)
        float l[4] = {0.f, 0.f, 0.f, 0.f};
        {
            const float4* xrow = (const float4*)(xs + n_loc * XS_PAD);
#pragma unroll 2
            for (int d4 = 0; d4 < 64; d4++) {
                float4 xv = xrow[d4];
#pragma unroll
                for (int j = 0; j < 4; j++) {
                    float4 qv = *(const float4*)(qsg + (s0 + j) * QS_PAD + 4 * d4);
                    l[j] += qv.x * xv.x + qv.y * xv.y + qv.z * xv.z + qv.w * xv.w;
                }
            }
        }
#pragma unroll
        for (int j = 0; j < 4; j++) l[j] *= 0.0625f;
        if (g == 3) l[3] = -1e30f;     // slot 15 doesn't exist
        float mx = fmaxf(fmaxf(l[0], l[1]), fmaxf(l[2], l[3]));
        mx = fmaxf(mx, __shfl_xor_sync(0xffffffffu, mx, 1));
        mx = fmaxf(mx, __shfl_xor_sync(0xffffffffu, mx, 2));
        float lsum = 0.f;
#pragma unroll
        for (int j = 0; j < 4; j++) { l[j] = __expf(l[j] - mx); lsum += l[j]; }
        lsum += __shfl_xor_sync(0xffffffffu, lsum, 1);
        lsum += __shfl_xor_sync(0xffffffffu, lsum, 2);
        float inv = 1.0f / lsum;
#pragma unroll
        for (int j = 0; j < 4; j++)
            as_[(s0 + j) * AS_PAD + n_loc] = l[j] * inv;
        __syncthreads();

        if (final_pass) {
            // coalesced attn write from smem
            size_t nglob = (size_t)chunk * (NSUB * 64) + sub * 64;
            for (int i = t; i < Kk * 64; i += 256) {
                int s = i >> 6, n = i & 63;
                attn_out[((size_t)(b * Kk + s)) * Nn + nglob + n] = as_[s * AS_PAD + n];
            }
            continue;
        }

        // phase 2: acc[s] += Σ_n as[s][n] · x̂[n][d=t]
#pragma unroll
        for (int nr = 0; nr < 64; nr += 8) {
            float xr[8];
#pragma unroll
            for (int i = 0; i < 8; i++) xr[i] = xs[(nr + i) * XS_PAD + t];
#pragma unroll
            for (int s = 0; s < Kk; s++) {
                float4 a0 = *(const float4*)(as_ + s * AS_PAD + nr);
                float4 a1 = *(const float4*)(as_ + s * AS_PAD + nr + 4);
                acc[s] += a0.x * xr[0] + a0.y * xr[1] + a0.z * xr[2] + a0.w * xr[3]
                        + a1.x * xr[4] + a1.y * xr[5] + a1.z * xr[6] + a1.w * xr[7];
            }
        }
        // partial row-sums (15 threads)
        if (t < Kk) {
            float s64 = 0.f;
#pragma unroll 8
            for (int n = 0; n < 64; n++) s64 += as_[t * AS_PAD + n];
            psum += s64;
        }
    }

    if (!final_pass) {
#pragma unroll
        for (int s = 0; s < Kk; s++)
            g_updpart[((size_t)chunk * BK_TOT + b * Kk + s) * Dd + t] = acc[s];
        if (t < Kk)
            g_part[(b * Kk + t) * NCH + chunk] = psum;
    }
}

// ---------------- fused slot update: U-reduce → GRU → MLP → LN → q ----------------
__global__ __launch_bounds__(256) void slot_update_kernel(
    const float* __restrict__ whh, const float* __restrict__ w1,
    const float* __restrict__ w2,
    const float* __restrict__ bih, const float* __restrict__ bhh,
    const float* __restrict__ b1, const float* __restrict__ b2,
    const float* __restrict__ lnm_w, const float* __restrict__ lnm_b,
    const float* __restrict__ lns_w, const float* __restrict__ lns_b) {
    __shared__ float u_s[8][256];
    __shared__ float h_s[8][256];
    __shared__ float a_s[8][256];
    __shared__ float h1_s[8][512];
    __shared__ float inv_s[8];
    int t = threadIdx.x, lane = t & 31, wid = t >> 5;
    int row0 = blockIdx.x * 8;

#pragma unroll
    for (int r = 0; r < 8; r++) h_s[r][t] = g_slots[(size_t)(row0 + r) * Dd + t];
    if (t < 8) {
        float s = 0.f;
#pragma unroll
        for (int c = 0; c < NCH; c++) s += g_part[(row0 + t) * NCH + c];
        inv_s[t] = 1.0f / (s + 1e-8f);
    }
    __syncthreads();
#pragma unroll
    for (int r = 0; r < 8; r++) {
        float a = 0.f;
#pragma unroll
        for (int c = 0; c < NCH; c++)
            a += g_updpart[((size_t)c * BK_TOT + row0 + r) * Dd + t];
        u_s[r][t] = a * inv_s[r];
    }
    __syncthreads();

    float ri[8] = {0}, rh[8] = {0}, zi[8] = {0}, zh[8] = {0}, ni[8] = {0}, nh[8] = {0};
    dot4<64>(ri, &u_s[0][0], 256, g_wiv + (size_t)t * Dd);
    dot4<64>(zi, &u_s[0][0], 256, g_wiv + (size_t)(256 + t) * Dd);
    dot4<64>(ni, &u_s[0][0], 256, g_wiv + (size_t)(512 + t) * Dd);
    dot4<64>(rh, &h_s[0][0], 256, whh + (size_t)t * Dd);
    dot4<64>(zh, &h_s[0][0], 256, whh + (size_t)(256 + t) * Dd);
    dot4<64>(nh, &h_s[0][0], 256, whh + (size_t)(512 + t) * Dd);
    float bir = bih[t], bhr = bhh[t];
    float biz = bih[256 + t], bhz = bhh[256 + t];
    float bin = bih[512 + t], bhn = bhh[512 + t];
    __syncthreads();
#pragma unroll
    for (int r = 0; r < 8; r++) {
        float rg = sigmoidf_(ri[r] + bir + rh[r] + bhr);
        float zg = sigmoidf_(zi[r] + biz + zh[r] + bhz);
        float ng = tanhf(ni[r] + bin + rg * (nh[r] + bhn));
        h_s[r][t] = (1.0f - zg) * ng + zg * h_s[r][t];
    }
    __syncthreads();
    warp_ln_row(&h_s[wid][0], &a_s[wid][0], lnm_w, lnm_b, lane);
    __syncthreads();
    float m0[8] = {0}, m1[8] = {0};
    dot4<64>(m0, &a_s[0][0], 256, w1 + (size_t)t * Dd);
    dot4<64>(m1, &a_s[0][0], 256, w1 + (size_t)(256 + t) * Dd);
    float b1a = b1[t], b1b = b1[256 + t];
#pragma unroll
    for (int r = 0; r < 8; r++) {
        h1_s[r][t] = fmaxf(m0[r] + b1a, 0.f);
        h1_s[r][256 + t] = fmaxf(m1[r] + b1b, 0.f);
    }
    __syncthreads();
    float m2[8] = {0};
    dot4<128>(m2, &h1_s[0][0], 512, w2 + (size_t)t * Hh);
    float b2t = b2[t];
#pragma unroll
    for (int r = 0; r < 8; r++) {
        float ns = h_s[r][t] + m2[r] + b2t;
        g_slots[(size_t)(row0 + r) * Dd + t] = ns;
        a_s[r][t] = ns;
    }
    __syncthreads();
    warp_ln_row(&a_s[wid][0], &u_s[wid][0], lns_w, lns_b, lane);
    __syncthreads();
    float qa[8] = {0};
    dot4<64>(qa, &u_s[0][0], 256, g_wqk + (size_t)t * Dd);
#pragma unroll
    for (int r = 0; r < 8; r++) g_q[(size_t)(row0 + r) * Dd + t] = qa[r];
}

__global__ void copy_kernel(const float* __restrict__ src, float* __restrict__ dst, int n) {
    int i = blockIdx.x * 256 + threadIdx.x;
    if (i < n) dst[i] = src[i];
}

// ---------------- host orchestration ----------------
extern "C" void kernel_launch(void* const* d_in, const int* in_sizes, int n_in,
                              void* d_out, int out_size) {
    const float* inputs        = (const float*)d_in[0];
    const float* slot_noise    = (const float*)d_in[1];
    const float* slots_mu      = (const float*)d_in[2];
    const float* slots_logsig  = (const float*)d_in[3];
    const float* Wq            = (const float*)d_in[4];
    const float* Wk            = (const float*)d_in[5];
    const float* Wv            = (const float*)d_in[6];
    const float* w_ih          = (const float*)d_in[7];
    const float* w_hh          = (const float*)d_in[8];
    const float* b_ih          = (const float*)d_in[9];
    const float* b_hh          = (const float*)d_in[10];
    const float* mlp_w1        = (const float*)d_in[11];
    const float* mlp_b1        = (const float*)d_in[12];
    const float* mlp_w2        = (const float*)d_in[13];
    const float* mlp_b2        = (const float*)d_in[14];
    const float* ln_in_w       = (const float*)d_in[15];
    const float* ln_in_b       = (const float*)d_in[16];
    const float* ln_s_w        = (const float*)d_in[17];
    const float* ln_s_b        = (const float*)d_in[18];
    const float* ln_m_w        = (const float*)d_in[19];
    const float* ln_m_b        = (const float*)d_in[20];
    float* out = (float*)d_out;

    float *p_xln, *p_wqk, *p_wiv, *p_q, *p_slots;
    cudaGetSymbolAddress((void**)&p_xln, g_xln);
    cudaGetSymbolAddress((void**)&p_wqk, g_wqk);
    cudaGetSymbolAddress((void**)&p_wiv, g_wiv);
    cudaGetSymbolAddress((void**)&p_q, g_q);
    cudaGetSymbolAddress((void**)&p_slots, g_slots);

    const int attn_smem = SM_TOTAL * 4;   // 104208 bytes
    cudaFuncSetAttribute(attn_pass_kernel,
                         cudaFuncAttributeMaxDynamicSharedMemorySize, attn_smem);

    ln_apply_kernel<<<BN_TOT / 8, dim3(32, 8)>>>(inputs, p_xln, ln_in_w, ln_in_b);
    atb_kernel<<<dim3(4, 4), 256>>>(Wk, Wq, p_wqk);
    ab_kernel<<<dim3(12, 4), 256>>>(w_ih, Wv, p_wiv);
    slots_init_kernel<<<BK_TOT, 256>>>(slots_mu, slots_logsig, slot_noise);
    slot_lnq_kernel<<<120, 256>>>(ln_s_w, ln_s_b);

    for (int it = 0; it < 3; it++) {
        attn_pass_kernel<<<dim3(NCH, Bb), 256, attn_smem>>>(p_q, p_xln, nullptr, 0);
        slot_update_kernel<<<120, 256>>>(w_hh, mlp_w1, mlp_w2, b_ih, b_hh,
                                         mlp_b1, mlp_b2, ln_m_w, ln_m_b, ln_s_w, ln_s_b);
    }

    attn_pass_kernel<<<dim3(NCH, Bb), 256, attn_smem>>>(p_q, p_xln, out + BK_TOT * Dd, 1);
    copy_kernel<<<960, 256>>>(p_slots, out, BK_TOT * Dd);
}

// round 11
// speedup vs baseline: 1.2464x; 1.2464x over previous
#include <cuda_runtime.h>
#include <math.h>
#include <stdint.h>

// SlotAttention GB300 — Round 10: R7 structure (best) with surgical phase-1 fix:
// 4 threads cooperate per n-row (lane g takes d4 ≡ g mod 4) → warp LDG touches
// 8 lines instead of 32 (4x fewer L1tex wavefronts); logits reduced via 2 bfly
// shuffles. Rowsums via 15-thread smem sweep. __expf. Rest identical to R7.

#define Bb 64
#define Nn 4096
#define Dd 256
#define Kk 15
#define Hh 512
#define BN_TOT (Bb * Nn)   // 262144
#define BK_TOT (Bb * Kk)   // 960
#define NCH 16             // n-chunks per batch
#define CHN 256            // n per chunk
#define AS_STR 260         // as_ row stride (floats): 4-aligned, 260%32=4

// ---------------- scratch ----------------
__device__ float g_xln[(size_t)BN_TOT * Dd];      // 256 MiB
__device__ float g_wqk[Dd * Dd];                  // [e][d] = Σ_j Wk[j,e]·Wq[j,d]
__device__ float g_wiv[3 * Dd * Dd];              // [g][e] = Σ_d w_ih[g,d]·Wv[d,e]
__device__ float g_slots[BK_TOT * Dd];
__device__ float g_q[BK_TOT * Dd];
__device__ float g_part[BK_TOT * NCH];
__device__ float g_updpart[(size_t)NCH * BK_TOT * Dd];  // 15.7 MB

// ---------------- helpers ----------------
__device__ __forceinline__ float warp_sum(float v) {
#pragma unroll
    for (int o = 16; o > 0; o >>= 1) v += __shfl_xor_sync(0xffffffffu, v, o);
    return v;
}
__device__ __forceinline__ float sigmoidf_(float x) { return 1.0f / (1.0f + __expf(-x)); }

template <int K4>
__device__ __forceinline__ void dot4(float acc[8], const float* S, int srow,
                                     const float* __restrict__ Wrow) {
    const float4* w4 = (const float4*)Wrow;
#pragma unroll 4
    for (int d4 = 0; d4 < K4; d4++) {
        float4 w = w4[d4];
#pragma unroll
        for (int r = 0; r < 8; r++) {
            const float4 sv = *(const float4*)(S + r * srow + d4 * 4);
            acc[r] += sv.x * w.x + sv.y * w.y + sv.z * w.z + sv.w * w.w;
        }
    }
}

__device__ __forceinline__ void warp_ln_row(const float* src, float* dst,
                                            const float* __restrict__ w,
                                            const float* __restrict__ b, int lane) {
    float vals[8];
    float s = 0.f, s2 = 0.f;
#pragma unroll
    for (int k = 0; k < 8; k++) {
        float v = src[lane + 32 * k];
        vals[k] = v; s += v; s2 += v * v;
    }
    s = warp_sum(s); s2 = warp_sum(s2);
    float m = s * (1.0f / 256.0f);
    float rs = rsqrtf(s2 * (1.0f / 256.0f) - m * m + 1e-5f);
#pragma unroll
    for (int k = 0; k < 8; k++) {
        int d = lane + 32 * k;
        dst[d] = (vals[k] - m) * rs * w[d] + b[d];
    }
}

// ---------------- big LN over inputs ----------------
__global__ void ln_apply_kernel(const float* __restrict__ x, float* __restrict__ y,
                                const float* __restrict__ w, const float* __restrict__ bb) {
    int row = blockIdx.x * 8 + threadIdx.y;
    int lane = threadIdx.x;
    warp_ln_row(x + (size_t)row * Dd, y + (size_t)row * Dd, w, bb, lane);
}

// ---------------- precompute: C[e][d] = Σ_j X[j][e]·Y[j][d]  (XᵀY) ----------------
__global__ __launch_bounds__(256) void atb_kernel(const float* __restrict__ X,
                                                  const float* __restrict__ Y,
                                                  float* __restrict__ C) {
    __shared__ float Xs[16][68];
    __shared__ float Ys[16][68];
    int e0 = blockIdx.x * 64, d0 = blockIdx.y * 64;
    int tid = threadIdx.x;
    int row_t = tid >> 4, col_t = tid & 15;
    int jr = tid >> 4, c4 = (tid & 15) << 2;
    float acc[4][4];
#pragma unroll
    for (int i = 0; i < 4; i++)
#pragma unroll
        for (int j = 0; j < 4; j++) acc[i][j] = 0.f;
    for (int jb = 0; jb < 256; jb += 16) {
        float4 xv = *(const float4*)(X + (size_t)(jb + jr) * Dd + e0 + c4);
        Xs[jr][c4 + 0] = xv.x; Xs[jr][c4 + 1] = xv.y;
        Xs[jr][c4 + 2] = xv.z; Xs[jr][c4 + 3] = xv.w;
        float4 yv = *(const float4*)(Y + (size_t)(jb + jr) * Dd + d0 + c4);
        Ys[jr][c4 + 0] = yv.x; Ys[jr][c4 + 1] = yv.y;
        Ys[jr][c4 + 2] = yv.z; Ys[jr][c4 + 3] = yv.w;
        __syncthreads();
#pragma unroll
        for (int k = 0; k < 16; k++)
#pragma unroll
            for (int i = 0; i < 4; i++)
#pragma unroll
                for (int j = 0; j < 4; j++)
                    acc[i][j] += Xs[k][row_t * 4 + i] * Ys[k][col_t * 4 + j];
        __syncthreads();
    }
#pragma unroll
    for (int i = 0; i < 4; i++)
#pragma unroll
        for (int j = 0; j < 4; j++)
            C[(size_t)(e0 + row_t * 4 + i) * Dd + d0 + col_t * 4 + j] = acc[i][j];
}

// ---------------- precompute: C[g][e] = Σ_d A[g][d]·B[d][e]  (A·B) ----------------
__global__ __launch_bounds__(256) void ab_kernel(const float* __restrict__ A,
                                                 const float* __restrict__ B,
                                                 float* __restrict__ C) {
    __shared__ float As[16][68];
    __shared__ float Bs[16][68];
    int g0 = blockIdx.x * 64, e0 = blockIdx.y * 64;
    int tid = threadIdx.x;
    int row_t = tid >> 4, col_t = tid & 15;
    int r = tid >> 2, k4 = (tid & 3) << 2;
    int jr = tid >> 4, c4 = (tid & 15) << 2;
    float acc[4][4];
#pragma unroll
    for (int i = 0; i < 4; i++)
#pragma unroll
        for (int j = 0; j < 4; j++) acc[i][j] = 0.f;
    for (int db = 0; db < 256; db += 16) {
        float4 av = *(const float4*)(A + (size_t)(g0 + r) * Dd + db + k4);
        As[k4 + 0][r] = av.x; As[k4 + 1][r] = av.y;
        As[k4 + 2][r] = av.z; As[k4 + 3][r] = av.w;
        float4 bv = *(const float4*)(B + (size_t)(db + jr) * Dd + e0 + c4);
        Bs[jr][c4 + 0] = bv.x; Bs[jr][c4 + 1] = bv.y;
        Bs[jr][c4 + 2] = bv.z; Bs[jr][c4 + 3] = bv.w;
        __syncthreads();
#pragma unroll
        for (int k = 0; k < 16; k++)
#pragma unroll
            for (int i = 0; i < 4; i++)
#pragma unroll
                for (int j = 0; j < 4; j++)
                    acc[i][j] += As[k][row_t * 4 + i] * Bs[k][col_t * 4 + j];
        __syncthreads();
    }
#pragma unroll
    for (int i = 0; i < 4; i++)
#pragma unroll
        for (int j = 0; j < 4; j++)
            C[(size_t)(g0 + row_t * 4 + i) * Dd + e0 + col_t * 4 + j] = acc[i][j];
}

// ---------------- slots init ----------------
__global__ void slots_init_kernel(const float* __restrict__ mu,
                                  const float* __restrict__ ls,
                                  const float* __restrict__ noise) {
    int i = blockIdx.x * 256 + threadIdx.x;
    int kd = i % (Kk * Dd);
    g_slots[i] = mu[kd] + __expf(ls[kd]) * noise[i];
}

// ---------------- ln_slots + q (before first iteration) ----------------
__global__ __launch_bounds__(256) void slot_lnq_kernel(const float* __restrict__ lns_w,
                                                       const float* __restrict__ lns_b) {
    __shared__ float a_s[8][256];
    int t = threadIdx.x, lane = t & 31, wid = t >> 5;
    int row0 = blockIdx.x * 8;
    warp_ln_row(g_slots + (size_t)(row0 + wid) * Dd, &a_s[wid][0], lns_w, lns_b, lane);
    __syncthreads();
    float qa[8] = {0, 0, 0, 0, 0, 0, 0, 0};
    dot4<64>(qa, &a_s[0][0], 256, g_wqk + (size_t)t * Dd);
#pragma unroll
    for (int r = 0; r < 8; r++) g_q[(size_t)(row0 + r) * Dd + t] = qa[r];
}

// ---------------- fused attention pass (4 threads per n-row in phase 1) -------
// grid (NCH, Bb), block 256. Phase 1: 4 stripes of 64 n; thread (n_rel, g)
// accumulates d4 ≡ g (mod 4), bfly-reduce over lanes 1,2. Phase 2: thread=d.
__global__ __launch_bounds__(256) void attn_pass_kernel(const float* __restrict__ q,
                                                        const float* __restrict__ xln,
                                                        float* __restrict__ attn_out,
                                                        int final_pass) {
    __shared__ float qs[Kk * Dd];
    __shared__ float as_[Kk * AS_STR];
    int b = blockIdx.y, chunk = blockIdx.x, t = threadIdx.x;
    int g = t & 3, nrel = t >> 2;     // 4 lanes per row, 64 rows per stripe

    const float4* qb = (const float4*)(q + (size_t)b * Kk * Dd);
    float4* qs4 = (float4*)qs;
    for (int i = t; i < Kk * 64; i += 256) qs4[i] = qb[i];
    __syncthreads();

    size_t nbase = (size_t)b * Nn + chunk * CHN;

#pragma unroll
    for (int stripe = 0; stripe < 4; stripe++) {
        int n_loc = stripe * 64 + nrel;
        const float4* xr = (const float4*)(xln + (nbase + n_loc) * Dd);
        float l[Kk];
#pragma unroll
        for (int s = 0; s < Kk; s++) l[s] = 0.f;
#pragma unroll 4
        for (int i = 0; i < 16; i++) {
            int d4 = 4 * i + g;                  // lane g covers d4 ≡ g (mod 4)
            float4 xv = xr[d4];
#pragma unroll
            for (int s = 0; s < Kk; s++) {
                float4 qv = qs4[s * 64 + d4];
                l[s] += qv.x * xv.x + qv.y * xv.y + qv.z * xv.z + qv.w * xv.w;
            }
        }
        // reduce partial logits across the 4 lanes of this row
#pragma unroll
        for (int s = 0; s < Kk; s++) {
            l[s] += __shfl_xor_sync(0xffffffffu, l[s], 1);
            l[s] += __shfl_xor_sync(0xffffffffu, l[s], 2);
        }
        float mx = -1e30f;
#pragma unroll
        for (int s = 0; s < Kk; s++) { l[s] *= 0.0625f; mx = fmaxf(mx, l[s]); }
        float sum = 0.f;
#pragma unroll
        for (int s = 0; s < Kk; s++) { l[s] = __expf(l[s] - mx); sum += l[s]; }
        float inv = 1.0f / sum;
        // lane g writes slots g, g+4, g+8, g+12 → conflict-free banks
#pragma unroll
        for (int s = g; s < Kk; s += 4)
            as_[s * AS_STR + n_loc] = l[s] * inv;
    }
    __syncthreads();

    if (final_pass) {
        for (int i = t; i < Kk * CHN; i += 256) {
            int s = i >> 8, n = i & 255;
            attn_out[((size_t)(b * Kk + s)) * Nn + chunk * CHN + n] = as_[s * AS_STR + n];
        }
        return;
    }

    // partial rowsums: 15 threads sweep their slot row (2-way bank conflicts max)
    if (t < Kk) {
        float ps = 0.f;
#pragma unroll 8
        for (int n = 0; n < CHN; n++) ps += as_[t * AS_STR + n];
        g_part[(b * Kk + t) * NCH + chunk] = ps;
    }

    // phase 2: U_partial[s][d=t] = Σ_n as[s][n]·x̂[n][d]  (chunk L2-hot)
    float acc[Kk];
#pragma unroll
    for (int s = 0; s < Kk; s++) acc[s] = 0.f;
    const float* xp = xln + nbase * Dd + t;
#pragma unroll 2
    for (int n4 = 0; n4 < CHN / 4; n4++) {
        float x0 = xp[(4 * n4 + 0) * Dd];
        float x1 = xp[(4 * n4 + 1) * Dd];
        float x2 = xp[(4 * n4 + 2) * Dd];
        float x3 = xp[(4 * n4 + 3) * Dd];
#pragma unroll
        for (int s = 0; s < Kk; s++) {
            float4 a4 = *(const float4*)(as_ + s * AS_STR + 4 * n4);
            acc[s] += a4.x * x0 + a4.y * x1 + a4.z * x2 + a4.w * x3;
        }
    }
#pragma unroll
    for (int s = 0; s < Kk; s++)
        g_updpart[((size_t)chunk * BK_TOT + b * Kk + s) * Dd + t] = acc[s];
}

// ---------------- fused slot update: U-reduce → GRU → MLP → LN → q ----------------
__global__ __launch_bounds__(256) void slot_update_kernel(
    const float* __restrict__ whh, const float* __restrict__ w1,
    const float* __restrict__ w2,
    const float* __restrict__ bih, const float* __restrict__ bhh,
    const float* __restrict__ b1, const float* __restrict__ b2,
    const float* __restrict__ lnm_w, const float* __restrict__ lnm_b,
    const float* __restrict__ lns_w, const float* __restrict__ lns_b) {
    __shared__ float u_s[8][256];
    __shared__ float h_s[8][256];
    __shared__ float a_s[8][256];
    __shared__ float h1_s[8][512];
    __shared__ float inv_s[8];
    int t = threadIdx.x, lane = t & 31, wid = t >> 5;
    int row0 = blockIdx.x * 8;

#pragma unroll
    for (int r = 0; r < 8; r++) h_s[r][t] = g_slots[(size_t)(row0 + r) * Dd + t];
    if (t < 8) {
        float s = 0.f;
#pragma unroll
        for (int c = 0; c < NCH; c++) s += g_part[(row0 + t) * NCH + c];
        inv_s[t] = 1.0f / (s + 1e-8f);
    }
    __syncthreads();
#pragma unroll
    for (int r = 0; r < 8; r++) {
        float a = 0.f;
#pragma unroll
        for (int c = 0; c < NCH; c++)
            a += g_updpart[((size_t)c * BK_TOT + row0 + r) * Dd + t];
        u_s[r][t] = a * inv_s[r];
    }
    __syncthreads();

    float ri[8] = {0}, rh[8] = {0}, zi[8] = {0}, zh[8] = {0}, ni[8] = {0}, nh[8] = {0};
    dot4<64>(ri, &u_s[0][0], 256, g_wiv + (size_t)t * Dd);
    dot4<64>(zi, &u_s[0][0], 256, g_wiv + (size_t)(256 + t) * Dd);
    dot4<64>(ni, &u_s[0][0], 256, g_wiv + (size_t)(512 + t) * Dd);
    dot4<64>(rh, &h_s[0][0], 256, whh + (size_t)t * Dd);
    dot4<64>(zh, &h_s[0][0], 256, whh + (size_t)(256 + t) * Dd);
    dot4<64>(nh, &h_s[0][0], 256, whh + (size_t)(512 + t) * Dd);
    float bir = bih[t], bhr = bhh[t];
    float biz = bih[256 + t], bhz = bhh[256 + t];
    float bin = bih[512 + t], bhn = bhh[512 + t];
    __syncthreads();
#pragma unroll
    for (int r = 0; r < 8; r++) {
        float rg = sigmoidf_(ri[r] + bir + rh[r] + bhr);
        float zg = sigmoidf_(zi[r] + biz + zh[r] + bhz);
        float ng = tanhf(ni[r] + bin + rg * (nh[r] + bhn));
        h_s[r][t] = (1.0f - zg) * ng + zg * h_s[r][t];
    }
    __syncthreads();
    warp_ln_row(&h_s[wid][0], &a_s[wid][0], lnm_w, lnm_b, lane);
    __syncthreads();
    float m0[8] = {0}, m1[8] = {0};
    dot4<64>(m0, &a_s[0][0], 256, w1 + (size_t)t * Dd);
    dot4<64>(m1, &a_s[0][0], 256, w1 + (size_t)(256 + t) * Dd);
    float b1a = b1[t], b1b = b1[256 + t];
#pragma unroll
    for (int r = 0; r < 8; r++) {
        h1_s[r][t] = fmaxf(m0[r] + b1a, 0.f);
        h1_s[r][256 + t] = fmaxf(m1[r] + b1b, 0.f);
    }
    __syncthreads();
    float m2[8] = {0};
    dot4<128>(m2, &h1_s[0][0], 512, w2 + (size_t)t * Hh);
    float b2t = b2[t];
#pragma unroll
    for (int r = 0; r < 8; r++) {
        float ns = h_s[r][t] + m2[r] + b2t;
        g_slots[(size_t)(row0 + r) * Dd + t] = ns;
        a_s[r][t] = ns;
    }
    __syncthreads();
    warp_ln_row(&a_s[wid][0], &u_s[wid][0], lns_w, lns_b, lane);
    __syncthreads();
    float qa[8] = {0};
    dot4<64>(qa, &u_s[0][0], 256, g_wqk + (size_t)t * Dd);
#pragma unroll
    for (int r = 0; r < 8; r++) g_q[(size_t)(row0 + r) * Dd + t] = qa[r];
}

__global__ void copy_kernel(const float* __restrict__ src, float* __restrict__ dst, int n) {
    int i = blockIdx.x * 256 + threadIdx.x;
    if (i < n) dst[i] = src[i];
}

// ---------------- host orchestration ----------------
extern "C" void kernel_launch(void* const* d_in, const int* in_sizes, int n_in,
                              void* d_out, int out_size) {
    const float* inputs        = (const float*)d_in[0];
    const float* slot_noise    = (const float*)d_in[1];
    const float* slots_mu      = (const float*)d_in[2];
    const float* slots_logsig  = (const float*)d_in[3];
    const float* Wq            = (const float*)d_in[4];
    const float* Wk            = (const float*)d_in[5];
    const float* Wv            = (const float*)d_in[6];
    const float* w_ih          = (const float*)d_in[7];
    const float* w_hh          = (const float*)d_in[8];
    const float* b_ih          = (const float*)d_in[9];
    const float* b_hh          = (const float*)d_in[10];
    const float* mlp_w1        = (const float*)d_in[11];
    const float* mlp_b1        = (const float*)d_in[12];
    const float* mlp_w2        = (const float*)d_in[13];
    const float* mlp_b2        = (const float*)d_in[14];
    const float* ln_in_w       = (const float*)d_in[15];
    const float* ln_in_b       = (const float*)d_in[16];
    const float* ln_s_w        = (const float*)d_in[17];
    const float* ln_s_b        = (const float*)d_in[18];
    const float* ln_m_w        = (const float*)d_in[19];
    const float* ln_m_b        = (const float*)d_in[20];
    float* out = (float*)d_out;

    float *p_xln, *p_wqk, *p_wiv, *p_q, *p_slots;
    cudaGetSymbolAddress((void**)&p_xln, g_xln);
    cudaGetSymbolAddress((void**)&p_wqk, g_wqk);
    cudaGetSymbolAddress((void**)&p_wiv, g_wiv);
    cudaGetSymbolAddress((void**)&p_q, g_q);
    cudaGetSymbolAddress((void**)&p_slots, g_slots);

    ln_apply_kernel<<<BN_TOT / 8, dim3(32, 8)>>>(inputs, p_xln, ln_in_w, ln_in_b);
    atb_kernel<<<dim3(4, 4), 256>>>(Wk, Wq, p_wqk);
    ab_kernel<<<dim3(12, 4), 256>>>(w_ih, Wv, p_wiv);
    slots_init_kernel<<<BK_TOT, 256>>>(slots_mu, slots_logsig, slot_noise);
    slot_lnq_kernel<<<120, 256>>>(ln_s_w, ln_s_b);

    for (int it = 0; it < 3; it++) {
        attn_pass_kernel<<<dim3(NCH, Bb), 256>>>(p_q, p_xln, nullptr, 0);
        slot_update_kernel<<<120, 256>>>(w_hh, mlp_w1, mlp_w2, b_ih, b_hh,
                                         mlp_b1, mlp_b2, ln_m_w, ln_m_b, ln_s_w, ln_s_b);
    }

    attn_pass_kernel<<<dim3(NCH, Bb), 256>>>(p_q, p_xln, out + BK_TOT * Dd, 1);
    copy_kernel<<<960, 256>>>(p_slots, out, BK_TOT * Dd);
}